// round 11
// baseline (speedup 1.0000x reference)
#include <cuda_runtime.h>
#include <cstdint>

// out[i, h=n*7+o, m] = sum_{j<48,k<3} W[i,j*3+k] * x[j, n*7+(o+k-1), m]
//   (term dropped when o+k-1 outside [0,7))
// x: (48,56,56) f32   W: (192,48,3) f32   out: (192,56,56) f32
//
// FFMA2 (fma.rn.f32x2, rt=2 -> 2x fp32 rate) mainloop.
// W pre-duplicated in smem as packed (w,w) u64 so the loop has zero pack-MOVs.
// 256 threads, __launch_bounds__(256,1) to prevent ptxas register strangulation.

#define JCH 48
#define KTAP 3
#define MW 56
#define MP 64            // padded m
#define BI 32            // output channels per block
#define NTHREADS 256

#define FMA_F32X2(d, a, b) \
    asm("fma.rn.f32x2 %0, %1, %2, %0;" : "+l"(d) : "l"(a), "l"(b))

__global__ __launch_bounds__(NTHREADS, 1)
void fold_conv_kernel(const float* __restrict__ x,
                      const float* __restrict__ W,
                      float* __restrict__ out)
{
    extern __shared__ float sm[];
    float*    xs  = sm;                               // [KTAP*JCH][MP] = 144*64 f32 (36 KB)
    uint64_t* wsd = (uint64_t*)(sm + KTAP * JCH * MP); // [JCH*KTAP][BI] u64 (36 KB)

    const int tid = threadIdx.x;
    const int h  = blockIdx.x;              // 0..55
    const int n  = h / 7;
    const int o  = h - n * 7;
    const int i0 = blockIdx.y * BI;         // 0..160 step 32

    // ---- x slab: 144 rows x 16 float4, coalesced, zero-padded ----
    {
        float4* xs4 = (float4*)xs;
        #pragma unroll
        for (int it = 0; it < (KTAP * JCH * 16) / NTHREADS; ++it) {   // 9 iters
            int idx = tid + it * NTHREADS;          // 0..2303
            int row = idx >> 4;                     // k*48+j
            int s   = idx & 15;                     // float4 slot
            int k   = row / JCH;
            int j   = row - k * JCH;
            int r   = o + k - 1;
            float4 v = make_float4(0.f, 0.f, 0.f, 0.f);
            if (r >= 0 && r < 7 && s < 14)
                v = *(const float4*)&x[(j * 56 + n * 7 + r) * 56 + s * 4];
            xs4[idx] = v;
        }
    }
    // ---- W tile: f4 gmem reads (coalesced), duplicate-pack to wsd[jk][ii] ----
    #pragma unroll
    for (int it = 0; it < 5; ++it) {                 // ceil(1152/256)
        int idx = tid + it * NTHREADS;               // f4 chunk id
        if (idx < BI * 36) {
            int ii = idx / 36;
            int q  = idx - ii * 36;                  // f4 slot within 144
            float4 v = *(const float4*)&W[(i0 + ii) * (JCH * KTAP) + q * 4];
            const float vr[4] = {v.x, v.y, v.z, v.w};
            #pragma unroll
            for (int t = 0; t < 4; ++t) {
                uint64_t p;
                asm("mov.b64 %0, {%1, %1};" : "=l"(p) : "r"(__float_as_uint(vr[t])));
                wsd[(q * 4 + t) * BI + ii] = p;
            }
        }
    }
    __syncthreads();

    // ---- mainloop: each thread computes 2i x 4m (2 packed m-pairs) ----
    const int mg  = tid & 15;               // m fastest -> coalesced stores
    const int ig  = tid >> 4;               // 16 i-groups
    const int m0  = mg * 4;                 // mg 14,15 hit padding (discarded)
    const int ii0 = ig * 2;

    uint64_t acc[2][2];
    acc[0][0] = acc[0][1] = acc[1][0] = acc[1][1] = 0ull;

    #pragma unroll 4
    for (int j = 0; j < JCH; ++j) {
        #pragma unroll
        for (int k = 0; k < KTAP; ++k) {
            const ulonglong2 xv = *(const ulonglong2*)&xs[(k * JCH + j) * MP + m0];
            const ulonglong2 wv = *(const ulonglong2*)&wsd[(j * 3 + k) * BI + ii0];
            FMA_F32X2(acc[0][0], wv.x, xv.x);
            FMA_F32X2(acc[0][1], wv.x, xv.y);
            FMA_F32X2(acc[1][0], wv.y, xv.x);
            FMA_F32X2(acc[1][1], wv.y, xv.y);
        }
    }

    // ---- store (skip padded m-groups; 16B-aligned) ----
    if (m0 < MW) {
        #pragma unroll
        for (int a = 0; a < 2; ++a) {
            const int i = i0 + ii0 + a;
            ulonglong2 v;
            v.x = acc[a][0];
            v.y = acc[a][1];
            *(ulonglong2*)&out[i * 3136 + h * 56 + m0] = v;
        }
    }
}

extern "C" void kernel_launch(void* const* d_in, const int* in_sizes, int n_in,
                              void* d_out, int out_size)
{
    const float* x = (const float*)d_in[0];   // 48*56*56
    const float* W = (const float*)d_in[1];   // 192*48*3
    float* out = (float*)d_out;               // 192*56*56

    const int smem = (KTAP * JCH * MP) * 4 + (JCH * KTAP * BI) * 8; // 73728 B
    static bool attr_set = false;
    if (!attr_set) {
        cudaFuncSetAttribute(fold_conv_kernel,
                             cudaFuncAttributeMaxDynamicSharedMemorySize, smem);
        attr_set = true;
    }
    dim3 grid(56, 6);
    fold_conv_kernel<<<grid, NTHREADS, smem>>>(x, W, out);
}

// round 12
// speedup vs baseline: 1.1429x; 1.1429x over previous
#include <cuda_runtime.h>
#include <cstdint>

// out[i, h=n*7+o, m] = sum_{j<48,k<3} W[i,j*3+k] * x[j, n*7+(o+k-1), m]
//   (term dropped when o+k-1 outside [0,7))
// x: (48,56,56) f32   W: (192,48,3) f32   out: (192,56,56) f32
//
// FFMA2 mainloop, 8 independent packed accumulators (required: FFMA2 RAW
// latency needs >=8-deep acc rotation), W pre-duplicated in smem as (w,w)
// u64 pairs so the mainloop has zero pack-MOVs.

#define JCH 48
#define KTAP 3
#define MW 56
#define MP 64            // padded m
#define BI 32            // output channels per block
#define NTHREADS 128

#define FMA_F32X2(d, a, b) \
    asm("fma.rn.f32x2 %0, %1, %2, %0;" : "+l"(d) : "l"(a), "l"(b))

__global__ __launch_bounds__(NTHREADS)
void fold_conv_kernel(const float* __restrict__ x,
                      const float* __restrict__ W,
                      float* __restrict__ out)
{
    extern __shared__ float sm[];
    float*    xs  = sm;                                // [KTAP*JCH][MP] f32 (36 KB)
    uint64_t* wsd = (uint64_t*)(sm + KTAP * JCH * MP); // [JCH*KTAP][BI] u64 (36 KB)

    const int tid = threadIdx.x;
    const int h  = blockIdx.x;              // 0..55
    const int n  = h / 7;
    const int o  = h - n * 7;
    const int i0 = blockIdx.y * BI;         // 0..160 step 32

    // ---- x slab: 144 rows x 16 float4, coalesced, zero-padded ----
    {
        float4* xs4 = (float4*)xs;
        #pragma unroll
        for (int it = 0; it < (KTAP * JCH * 16) / NTHREADS; ++it) {   // 18 iters
            int idx = tid + it * NTHREADS;          // 0..2303
            int row = idx >> 4;                     // k*48+j
            int s   = idx & 15;                     // float4 slot
            int k   = row / JCH;
            int j   = row - k * JCH;
            int r   = o + k - 1;
            float4 v = make_float4(0.f, 0.f, 0.f, 0.f);
            if (r >= 0 && r < 7 && s < 14)
                v = *(const float4*)&x[(j * 56 + n * 7 + r) * 56 + s * 4];
            xs4[idx] = v;
        }
    }
    // ---- W tile: f4 gmem reads (coalesced), duplicate-pack to wsd[jk][ii] ----
    #pragma unroll
    for (int it = 0; it < (BI * 36) / NTHREADS; ++it) {   // 9 iters
        int idx = tid + it * NTHREADS;               // f4 chunk id, 0..1151
        int ii  = idx / 36;
        int q   = idx - ii * 36;                     // f4 slot within 144
        float4 v = *(const float4*)&W[(i0 + ii) * (JCH * KTAP) + q * 4];
        const float vr[4] = {v.x, v.y, v.z, v.w};
        #pragma unroll
        for (int t = 0; t < 4; ++t) {
            uint64_t p;
            asm("mov.b64 %0, {%1, %1};" : "=l"(p) : "r"(__float_as_uint(vr[t])));
            wsd[(q * 4 + t) * BI + ii] = p;
        }
    }
    __syncthreads();

    // ---- mainloop: each thread computes 4i x 4m (8 packed accumulators) ----
    const int mg  = tid & 15;               // m fastest -> coalesced stores
    const int ig  = tid >> 4;               // 8 i-groups
    const int m0  = mg * 4;                 // mg 14,15 hit padding (discarded)
    const int ii0 = ig * 4;

    uint64_t acc[4][2];                     // [i][m-pair]
    #pragma unroll
    for (int a = 0; a < 4; ++a) {
        acc[a][0] = 0ull;
        acc[a][1] = 0ull;
    }

    #pragma unroll 2
    for (int j = 0; j < JCH; ++j) {
        ulonglong2 xv[KTAP];                // (m0,m0+1),(m0+2,m0+3)
        ulonglong2 wv[KTAP][2];             // (i0..i1),(i2..i3) dup-packed
        #pragma unroll
        for (int k = 0; k < KTAP; ++k) {
            xv[k]    = *(const ulonglong2*)&xs[(k * JCH + j) * MP + m0];
            wv[k][0] = *(const ulonglong2*)&wsd[(j * 3 + k) * BI + ii0];
            wv[k][1] = *(const ulonglong2*)&wsd[(j * 3 + k) * BI + ii0 + 2];
        }
        #pragma unroll
        for (int k = 0; k < KTAP; ++k) {
            FMA_F32X2(acc[0][0], wv[k][0].x, xv[k].x);
            FMA_F32X2(acc[1][0], wv[k][0].y, xv[k].x);
            FMA_F32X2(acc[2][0], wv[k][1].x, xv[k].x);
            FMA_F32X2(acc[3][0], wv[k][1].y, xv[k].x);
            FMA_F32X2(acc[0][1], wv[k][0].x, xv[k].y);
            FMA_F32X2(acc[1][1], wv[k][0].y, xv[k].y);
            FMA_F32X2(acc[2][1], wv[k][1].x, xv[k].y);
            FMA_F32X2(acc[3][1], wv[k][1].y, xv[k].y);
        }
    }

    // ---- store (skip padded m-groups; 16B-aligned) ----
    if (m0 < MW) {
        #pragma unroll
        for (int a = 0; a < 4; ++a) {
            const int i = i0 + ii0 + a;
            ulonglong2 v;
            v.x = acc[a][0];
            v.y = acc[a][1];
            *(ulonglong2*)&out[i * 3136 + h * 56 + m0] = v;
        }
    }
}

extern "C" void kernel_launch(void* const* d_in, const int* in_sizes, int n_in,
                              void* d_out, int out_size)
{
    const float* x = (const float*)d_in[0];   // 48*56*56
    const float* W = (const float*)d_in[1];   // 192*48*3
    float* out = (float*)d_out;               // 192*56*56

    const int smem = (KTAP * JCH * MP) * 4 + (JCH * KTAP * BI) * 8; // 73728 B
    static bool attr_set = false;
    if (!attr_set) {
        cudaFuncSetAttribute(fold_conv_kernel,
                             cudaFuncAttributeMaxDynamicSharedMemorySize, smem);
        attr_set = true;
    }
    dim3 grid(56, 6);
    fold_conv_kernel<<<grid, NTHREADS, smem>>>(x, W, out);
}

// round 13
// speedup vs baseline: 2.7059x; 2.3676x over previous
#include <cuda_runtime.h>

// out[i, h=n*7+o, m] = sum_{j<48,k<3} W[i,j*3+k] * x[j, n*7+(o+k-1), m]
//   (term dropped when o+k-1 outside [0,7))
// x: (48,56,56) f32   W: (192,48,3) f32   out: (192,56,56) f32
//
// R2 config + vectorized W: thread's 4 i's strided by 8 so W LDS.128 from
// layout ws4[q][33] are bank-conflict-free; j unrolled x4 so W f4 chunks
// align with jk quads. Per 4j: 12 x-LDS.128 + 12 W-LDS.128 + 192 FFMA.

#define JCH 48
#define KTAP 3
#define MW 56
#define MP 64            // padded m
#define BI 32            // output channels per block
#define NTHREADS 128
#define NQ 36            // f4 chunks along jk (144/4)
#define WROW 33          // ws4 row stride in float4 (odd -> conflict-free STS)

__global__ __launch_bounds__(NTHREADS)
void fold_conv_kernel(const float* __restrict__ x,
                      const float* __restrict__ W,
                      float* __restrict__ out)
{
    extern __shared__ float sm[];
    float*  xs  = sm;                              // [KTAP*JCH][MP] f32 (36 KB)
    float4* ws4 = (float4*)(sm + KTAP * JCH * MP); // [NQ][WROW] f4  (19 KB)

    const int tid = threadIdx.x;
    const int h  = blockIdx.x;              // 0..55
    const int n  = h / 7;
    const int o  = h - n * 7;
    const int i0 = blockIdx.y * BI;         // 0..160 step 32

    // ---- x slab: 144 rows x 16 float4, coalesced, zero-padded ----
    {
        float4* xs4 = (float4*)xs;
        #pragma unroll
        for (int it = 0; it < (KTAP * JCH * 16) / NTHREADS; ++it) {   // 18 iters
            int idx = tid + it * NTHREADS;          // 0..2303
            int row = idx >> 4;                     // k*48+j
            int s   = idx & 15;                     // float4 slot
            int k   = row / JCH;
            int j   = row - k * JCH;
            int r   = o + k - 1;
            float4 v = make_float4(0.f, 0.f, 0.f, 0.f);
            if (r >= 0 && r < 7 && s < 14)
                v = *(const float4*)&x[(j * 56 + n * 7 + r) * 56 + s * 4];
            xs4[idx] = v;
        }
    }
    // ---- W tile: f4 gmem reads (coalesced), STS f4 to ws4[q][ii] ----
    #pragma unroll
    for (int it = 0; it < (BI * NQ) / NTHREADS; ++it) {   // 9 iters
        int idx = tid + it * NTHREADS;               // 0..1151
        int ii  = idx / NQ;
        int q   = idx - ii * NQ;
        float4 v = *(const float4*)&W[(i0 + ii) * (JCH * KTAP) + q * 4];
        ws4[q * WROW + ii] = v;                      // lanes: q+1 -> +33 f4 -> bank+4
    }
    __syncthreads();

    // ---- mainloop: thread computes i in {i0+ig+8a} x 4m ----
    const int ig = tid & 7;                 // 8 i-groups (strided i)
    const int mg = tid >> 3;                // 16 m-groups, m fastest within warp
    const int m0 = mg * 4;                  // mg 14,15 hit padding (discarded)

    float acc[4][4];
    #pragma unroll
    for (int a = 0; a < 4; ++a)
        #pragma unroll
        for (int b = 0; b < 4; ++b)
            acc[a][b] = 0.0f;

    #pragma unroll 1
    for (int t = 0; t < 12; ++t) {          // 4 j per group
        // W: 3 chunks x 4 a-rows, conflict-free LDS.128
        float4 wv[3][4];
        #pragma unroll
        for (int c = 0; c < 3; ++c)
            #pragma unroll
            for (int a = 0; a < 4; ++a)
                wv[c][a] = ws4[(3 * t + c) * WROW + a * 8 + ig];
        // x: 12 rows (jk = 12t+e -> k = e%3, j = 4t + e/3), 1-wavefront LDS.128
        float4 xv[12];
        #pragma unroll
        for (int e = 0; e < 12; ++e) {
            const int row = (e % 3) * JCH + 4 * t + e / 3;
            xv[e] = *(const float4*)&xs[row * MP + m0];
        }
        #pragma unroll
        for (int c = 0; c < 3; ++c) {
            #pragma unroll
            for (int s = 0; s < 4; ++s) {
                const int e = 4 * c + s;
                const float xr[4] = {xv[e].x, xv[e].y, xv[e].z, xv[e].w};
                #pragma unroll
                for (int a = 0; a < 4; ++a) {
                    const float w = (s == 0) ? wv[c][a].x :
                                    (s == 1) ? wv[c][a].y :
                                    (s == 2) ? wv[c][a].z : wv[c][a].w;
                    acc[a][0] = fmaf(w, xr[0], acc[a][0]);
                    acc[a][1] = fmaf(w, xr[1], acc[a][1]);
                    acc[a][2] = fmaf(w, xr[2], acc[a][2]);
                    acc[a][3] = fmaf(w, xr[3], acc[a][3]);
                }
            }
        }
    }

    // ---- store (skip padded m-groups; 16B-aligned float4) ----
    if (m0 < MW) {
        #pragma unroll
        for (int a = 0; a < 4; ++a) {
            const int i = i0 + ig + a * 8;
            float4 v = {acc[a][0], acc[a][1], acc[a][2], acc[a][3]};
            *(float4*)&out[i * 3136 + h * 56 + m0] = v;
        }
    }
}

extern "C" void kernel_launch(void* const* d_in, const int* in_sizes, int n_in,
                              void* d_out, int out_size)
{
    const float* x = (const float*)d_in[0];   // 48*56*56
    const float* W = (const float*)d_in[1];   // 192*48*3
    float* out = (float*)d_out;               // 192*56*56

    const int smem = (KTAP * JCH * MP) * 4 + NQ * WROW * 16; // 36864 + 19008 = 55872 B
    static bool attr_set = false;
    if (!attr_set) {
        cudaFuncSetAttribute(fold_conv_kernel,
                             cudaFuncAttributeMaxDynamicSharedMemorySize, smem);
        attr_set = true;
    }
    dim3 grid(56, 6);
    fold_conv_kernel<<<grid, NTHREADS, smem>>>(x, W, out);
}